// round 13
// baseline (speedup 1.0000x reference)
#include <cuda_runtime.h>
#include <cuda_fp16.h>

#define D 128
#define NMAX 50048               // 782 * 64, covers MLP grid padding
#define PAD 64                   // bucket slots per dst
#define HASH_SIZE (1u << 21)
#define OVF_MAX 4096

// ---------------- device-global scratch (no allocations allowed) ------------
__device__ unsigned long long g_hash[HASH_SIZE];      // gen-tagged, never cleared
__device__ unsigned int g_gen;
__device__ float g_h[(size_t)NMAX * D];               // 25.6 MB
__device__ float g_h1[(size_t)NMAX * D];              // 25.6 MB (layer-1 output)
__device__ uint2 g_nf16[(size_t)NMAX * D / 4];        // 12.8 MB fp16 mirror
__device__ int g_cnt[NMAX];
__device__ int g_bucket[(size_t)NMAX * PAD];          // 12.8 MB
__device__ int g_ovf[OVF_MAX * 2];
__device__ int g_ovf_cnt;
__device__ int g_idx64;

// ---------------- packed f32x2 helpers (Blackwell FFMA2) --------------------
__device__ __forceinline__ unsigned long long ffma2(unsigned long long a,
                                                    unsigned long long b,
                                                    unsigned long long c) {
    unsigned long long d;
    asm("fma.rn.f32x2 %0, %1, %2, %3;" : "=l"(d) : "l"(a), "l"(b), "l"(c));
    return d;
}
__device__ __forceinline__ unsigned long long pack2(float lo, float hi) {
    unsigned long long r;
    asm("mov.b64 %0, {%1, %2};" : "=l"(r) : "f"(lo), "f"(hi));
    return r;
}
__device__ __forceinline__ void unpack2(unsigned long long v, float& lo, float& hi) {
    asm("mov.b64 {%0, %1}, %2;" : "=f"(lo), "=f"(hi) : "l"(v));
}
__device__ __forceinline__ __half2 h2_from_u32(unsigned int u) {
    return reinterpret_cast<const __half2&>(u);
}
__device__ __forceinline__ unsigned int u32_from_h2(__half2 h) {
    return reinterpret_cast<const unsigned int&>(h);
}

// ---- phase 0: zero counts, build fp16 mirror, detect index dtype -----------
__global__ void __launch_bounds__(256)
k_setup(const float4* __restrict__ nf, const unsigned int* __restrict__ src,
        int n4) {
    int i = blockIdx.x * blockDim.x + threadIdx.x;
    if (i < n4) {
        float4 a = nf[i];
        uint2 o;
        o.x = u32_from_h2(__float22half2_rn(make_float2(a.x, a.y)));
        o.y = u32_from_h2(__float22half2_rn(make_float2(a.z, a.w)));
        g_nf16[i] = o;
    }
    if (i < NMAX) g_cnt[i] = 0;
    if (i == 0) {
        g_ovf_cnt = 0;
        g_gen = g_gen + 1;
        int is64 = 1;
#pragma unroll
        for (int k = 0; k < 8; k++)
            if (src[2 * k + 1] != 0u) is64 = 0;
        g_idx64 = is64;
    }
}

// ---- phase 1: fused dedup + bucket fill (thread per edge) ------------------
__global__ void __launch_bounds__(256)
k_dedup_fill(const void* __restrict__ srcp, const void* __restrict__ dstp,
             int nE) {
    int e = blockIdx.x * blockDim.x + threadIdx.x;
    if (e >= nE) return;
    int s, d;
    if (g_idx64) {
        s = (int)((const long long*)srcp)[e];
        d = (int)((const long long*)dstp)[e];
    } else {
        s = ((const int*)srcp)[e];
        d = ((const int*)dstp)[e];
    }

    unsigned int gen = g_gen;
    unsigned int key = ((unsigned)s << 16) | (unsigned)d;
    unsigned long long want = ((unsigned long long)gen << 32) | key;
    unsigned int slot = (key * 0x9E3779B1u) >> (32 - 21);

    for (;;) {
        unsigned long long cur;
        asm volatile("ld.global.cg.u64 %0, [%1];"
                     : "=l"(cur) : "l"(&g_hash[slot]));
        if (cur == want) return;
        if ((unsigned int)(cur >> 32) != gen) {
            unsigned long long prev = atomicCAS(&g_hash[slot], cur, want);
            if (prev == cur) break;
            if (prev == want) return;
            if ((unsigned int)(prev >> 32) != gen) continue;
        }
        slot = (slot + 1) & (HASH_SIZE - 1);
    }
    int pos = atomicAdd(&g_cnt[d], 1);
    if (pos < PAD) {
        g_bucket[(size_t)d * PAD + pos] = s;
    } else {
        int o = atomicAdd(&g_ovf_cnt, 1);
        if (o < OVF_MAX) { g_ovf[2 * o] = s; g_ovf[2 * o + 1] = d; }
    }
}

// ---- phase 2: warp-per-dst fp16 gather-sum + (1+alpha)*x + fused overflow --
__global__ void __launch_bounds__(256)
k_agg(const float* __restrict__ nfeats, const float* __restrict__ alpha,
      int nrows) {
    int w = (int)((blockIdx.x * 256u + threadIdx.x) >> 5);
    int lane = threadIdx.x & 31;
    if (w >= nrows) return;

    const float4* nf4 = (const float4*)nfeats;
    float sc = 1.0f + alpha[0];

    float4 a = nf4[(size_t)w * 32 + lane];
    float4 acc = make_float4(a.x * sc, a.y * sc, a.z * sc, a.w * sc);

    int cnt = g_cnt[w];
    if (cnt > PAD) cnt = PAD;
    const int* bk = &g_bucket[(size_t)w * PAD];

#define ACC_H8(u)                                                         \
    do {                                                                  \
        float2 f0 = __half22float2(h2_from_u32((u).x));                   \
        float2 f1 = __half22float2(h2_from_u32((u).y));                   \
        acc.x += f0.x; acc.y += f0.y; acc.z += f1.x; acc.w += f1.y;       \
    } while (0)

    int j = 0;
    for (; j + 4 <= cnt; j += 4) {
        int s0 = bk[j], s1 = bk[j + 1], s2 = bk[j + 2], s3 = bk[j + 3];
        uint2 v0 = g_nf16[(size_t)s0 * 32 + lane];
        uint2 v1 = g_nf16[(size_t)s1 * 32 + lane];
        uint2 v2 = g_nf16[(size_t)s2 * 32 + lane];
        uint2 v3 = g_nf16[(size_t)s3 * 32 + lane];
        ACC_H8(v0); ACC_H8(v1); ACC_H8(v2); ACC_H8(v3);
    }
    for (; j < cnt; j++) {
        uint2 v0 = g_nf16[(size_t)bk[j] * 32 + lane];
        ACC_H8(v0);
    }
#undef ACC_H8

    int novf = g_ovf_cnt;
    if (novf > 0) {
        if (novf > OVF_MAX) novf = OVF_MAX;
        for (int k = 0; k < novf; k++) {
            if (g_ovf[2 * k + 1] == w) {
                int s = g_ovf[2 * k];
                float4 u = nf4[(size_t)s * 32 + lane];
                acc.x += u.x; acc.y += u.y; acc.z += u.z; acc.w += u.w;
            }
        }
    }

    ((float4*)g_h)[(size_t)w * 32 + lane] = acc;
}

// ---- phase 3: MLP layer, 64-row blocks, 8 rows x 4 cols per thread ---------
// Inner loop restructured to keep registers <= 64:
//   hoist 4x W ulonglong2 per 4-k (16 regs), rows inner with transient h
//   float4 (4 regs). acc = 16 ull (32 regs). -> 4 blocks/SM (32 warps).
// smem: W half [64][128] (32KB) + H half [64][64] (16KB) = 48.5KB.
// L1 wavefronts: 24 per 64 FFMA2 (w non-broadcast + h broadcast) -> not L1-bound.
template <bool RELU, bool GUARD>
__device__ __forceinline__ void
mlp_layer_body(const float* __restrict__ Wg, const float* __restrict__ bg,
               const float* __restrict__ gin, float* __restrict__ gout,
               int nrows) {
    extern __shared__ float smem[];
    float* sW = smem;                  // 8192 floats (64 k-rows x 128 cols)
    float* sH = smem + 8192;           // 4096 floats (64 rows x 64 k)

    int tid = threadIdx.x;
    int x = tid & 31;                  // col group: cols [4x, 4x+4)
    int y = tid >> 5;                  // row group: rows [8y, 8y+8)
    int row0 = blockIdx.x * 64;

    unsigned long long a01[8], a23[8];
    {
        float4 bv = *(const float4*)(bg + x * 4);
        unsigned long long i01 = pack2(bv.x, bv.y), i23 = pack2(bv.z, bv.w);
#pragma unroll
        for (int i = 0; i < 8; i++) { a01[i] = i01; a23[i] = i23; }
    }

#pragma unroll
    for (int phase = 0; phase < 2; phase++) {
        if (phase) __syncthreads();

        // fill W half: k rows [phase*64, phase*64+64), all 128 cols
        {
            const float4* wg4 = (const float4*)(Wg + phase * 64 * D);
            for (int i = tid; i < 2048; i += 256) ((float4*)sW)[i] = wg4[i];
        }
        // fill H half: 64 rows x k cols [phase*64, phase*64+64)
        for (int i = tid; i < 1024; i += 256) {
            int r = i >> 4, c4 = i & 15;
            ((float4*)sH)[i] =
                *(const float4*)(gin + (size_t)(row0 + r) * D + phase * 64 + c4 * 4);
        }
        __syncthreads();

        const float* hrow = sH + y * 8 * 64;
        const float* wcol = sW + x * 4;
#pragma unroll 2
        for (int k0 = 0; k0 < 64; k0 += 4) {
            // hoist 4 k-rows of W for this thread's 4 cols (16 regs)
            ulonglong2 wv0 = *(const ulonglong2*)(wcol + (k0 + 0) * D);
            ulonglong2 wv1 = *(const ulonglong2*)(wcol + (k0 + 1) * D);
            ulonglong2 wv2 = *(const ulonglong2*)(wcol + (k0 + 2) * D);
            ulonglong2 wv3 = *(const ulonglong2*)(wcol + (k0 + 3) * D);
#pragma unroll
            for (int i = 0; i < 8; i++) {
                float4 h = *(const float4*)(hrow + i * 64 + k0);  // broadcast
                unsigned long long h0 = pack2(h.x, h.x);
                a01[i] = ffma2(h0, wv0.x, a01[i]);
                a23[i] = ffma2(h0, wv0.y, a23[i]);
                unsigned long long h1 = pack2(h.y, h.y);
                a01[i] = ffma2(h1, wv1.x, a01[i]);
                a23[i] = ffma2(h1, wv1.y, a23[i]);
                unsigned long long h2 = pack2(h.z, h.z);
                a01[i] = ffma2(h2, wv2.x, a01[i]);
                a23[i] = ffma2(h2, wv2.y, a23[i]);
                unsigned long long h3 = pack2(h.w, h.w);
                a01[i] = ffma2(h3, wv3.x, a01[i]);
                a23[i] = ffma2(h3, wv3.y, a23[i]);
            }
        }
    }

#pragma unroll
    for (int i = 0; i < 8; i++) {
        int gr = row0 + y * 8 + i;
        if (!GUARD || gr < nrows) {
            float f0, f1, f2, f3;
            unpack2(a01[i], f0, f1); unpack2(a23[i], f2, f3);
            if (RELU) {
                f0 = fmaxf(f0, 0.f); f1 = fmaxf(f1, 0.f);
                f2 = fmaxf(f2, 0.f); f3 = fmaxf(f3, 0.f);
            }
            *(float4*)(gout + (size_t)gr * D + x * 4) =
                make_float4(f0, f1, f2, f3);
        }
    }
}

__global__ void __launch_bounds__(256, 4)
k_mlp1(const float* __restrict__ W1, const float* __restrict__ b1, int nrows) {
    mlp_layer_body<true, false>(W1, b1, g_h, g_h1, nrows);
}

__global__ void __launch_bounds__(256, 4)
k_mlp2(const float* __restrict__ W2, const float* __restrict__ b2,
       float* __restrict__ out, int nrows) {
    mlp_layer_body<false, true>(W2, b2, g_h1, out, nrows);
}

// ---------------- launch ----------------------------------------------------
#define MLP_SMEM (12288 * 4)     // 49152 bytes: W half 32KB + H half 16KB

extern "C" void kernel_launch(void* const* d_in, const int* in_sizes, int n_in,
                              void* d_out, int out_size) {
    const float* nfeats = (const float*)d_in[0];
    const void*  src    = d_in[1];
    const void*  dst    = d_in[2];
    const float* W1     = (const float*)d_in[3];
    const float* b1     = (const float*)d_in[4];
    const float* W2     = (const float*)d_in[5];
    const float* b2     = (const float*)d_in[6];
    const float* alpha  = (const float*)d_in[7];
    float* out = (float*)d_out;

    int nE    = in_sizes[1];
    int nrows = in_sizes[0] / D;
    int n4    = nrows * (D / 4);

    int setup_items = n4 > NMAX ? n4 : NMAX;
    k_setup<<<(setup_items + 255) / 256, 256>>>(
        (const float4*)nfeats, (const unsigned int*)src, n4);
    k_dedup_fill<<<(nE + 255) / 256, 256>>>(src, dst, nE);
    k_agg<<<(nrows + 7) / 8, 256>>>(nfeats, alpha, nrows);

    cudaFuncSetAttribute(k_mlp1, cudaFuncAttributeMaxDynamicSharedMemorySize,
                         MLP_SMEM);
    cudaFuncSetAttribute(k_mlp2, cudaFuncAttributeMaxDynamicSharedMemorySize,
                         MLP_SMEM);
    int nblk = (nrows + 63) / 64;
    k_mlp1<<<nblk, 256, MLP_SMEM>>>(W1, b1, nrows);
    k_mlp2<<<nblk, 256, MLP_SMEM>>>(W2, b2, out, nrows);
}

// round 14
// speedup vs baseline: 1.1364x; 1.1364x over previous
#include <cuda_runtime.h>
#include <cuda_fp16.h>

#define D 128
#define NMAX 50048               // 782 * 64, covers MLP grid padding
#define PAD 64                   // bucket slots per dst
#define HASH_SIZE (1u << 21)
#define OVF_MAX 4096

// ---------------- device-global scratch (no allocations allowed) ------------
__device__ unsigned long long g_hash[HASH_SIZE];      // gen-tagged, never cleared
__device__ unsigned int g_gen;
__device__ float g_h[(size_t)NMAX * D];               // 25.6 MB
__device__ uint2 g_nf16[(size_t)NMAX * D / 4];        // 12.8 MB fp16 mirror
__device__ int g_cnt[NMAX];
__device__ int g_bucket[(size_t)NMAX * PAD];          // 12.8 MB
__device__ int g_ovf[OVF_MAX * 2];
__device__ int g_ovf_cnt;
__device__ int g_idx64;

// ---------------- packed f32x2 helpers (Blackwell FFMA2) --------------------
__device__ __forceinline__ unsigned long long ffma2(unsigned long long a,
                                                    unsigned long long b,
                                                    unsigned long long c) {
    unsigned long long d;
    asm("fma.rn.f32x2 %0, %1, %2, %3;" : "=l"(d) : "l"(a), "l"(b), "l"(c));
    return d;
}
__device__ __forceinline__ unsigned long long pack2(float lo, float hi) {
    unsigned long long r;
    asm("mov.b64 %0, {%1, %2};" : "=l"(r) : "f"(lo), "f"(hi));
    return r;
}
__device__ __forceinline__ void unpack2(unsigned long long v, float& lo, float& hi) {
    asm("mov.b64 {%0, %1}, %2;" : "=f"(lo), "=f"(hi) : "l"(v));
}
__device__ __forceinline__ __half2 h2_from_u32(unsigned int u) {
    return reinterpret_cast<const __half2&>(u);
}
__device__ __forceinline__ unsigned int u32_from_h2(__half2 h) {
    return reinterpret_cast<const unsigned int&>(h);
}

// ---- phase 0: zero counts, build fp16 mirror, detect index dtype -----------
__global__ void __launch_bounds__(256)
k_setup(const float4* __restrict__ nf, const unsigned int* __restrict__ src,
        int n4) {
    int i = blockIdx.x * blockDim.x + threadIdx.x;
    if (i < n4) {
        float4 a = nf[i];
        uint2 o;
        o.x = u32_from_h2(__float22half2_rn(make_float2(a.x, a.y)));
        o.y = u32_from_h2(__float22half2_rn(make_float2(a.z, a.w)));
        g_nf16[i] = o;
    }
    if (i < NMAX) g_cnt[i] = 0;
    if (i == 0) {
        g_ovf_cnt = 0;
        g_gen = g_gen + 1;
        int is64 = 1;
#pragma unroll
        for (int k = 0; k < 8; k++)
            if (src[2 * k + 1] != 0u) is64 = 0;
        g_idx64 = is64;
    }
}

// ---- phase 1: fused dedup + bucket fill (thread per edge) ------------------
__global__ void __launch_bounds__(256)
k_dedup_fill(const void* __restrict__ srcp, const void* __restrict__ dstp,
             int nE) {
    int e = blockIdx.x * blockDim.x + threadIdx.x;
    if (e >= nE) return;
    int s, d;
    if (g_idx64) {
        s = (int)((const long long*)srcp)[e];
        d = (int)((const long long*)dstp)[e];
    } else {
        s = ((const int*)srcp)[e];
        d = ((const int*)dstp)[e];
    }

    unsigned int gen = g_gen;
    unsigned int key = ((unsigned)s << 16) | (unsigned)d;
    unsigned long long want = ((unsigned long long)gen << 32) | key;
    unsigned int slot = (key * 0x9E3779B1u) >> (32 - 21);

    for (;;) {
        unsigned long long cur;
        asm volatile("ld.global.cg.u64 %0, [%1];"
                     : "=l"(cur) : "l"(&g_hash[slot]));
        if (cur == want) return;
        if ((unsigned int)(cur >> 32) != gen) {
            unsigned long long prev = atomicCAS(&g_hash[slot], cur, want);
            if (prev == cur) break;
            if (prev == want) return;
            if ((unsigned int)(prev >> 32) != gen) continue;
        }
        slot = (slot + 1) & (HASH_SIZE - 1);
    }
    int pos = atomicAdd(&g_cnt[d], 1);
    if (pos < PAD) {
        g_bucket[(size_t)d * PAD + pos] = s;
    } else {
        int o = atomicAdd(&g_ovf_cnt, 1);
        if (o < OVF_MAX) { g_ovf[2 * o] = s; g_ovf[2 * o + 1] = d; }
    }
}

// ---- phase 2: warp-per-dst fp16 gather-sum + (1+alpha)*x + fused overflow --
__global__ void __launch_bounds__(256)
k_agg(const float* __restrict__ nfeats, const float* __restrict__ alpha,
      int nrows) {
    int w = (int)((blockIdx.x * 256u + threadIdx.x) >> 5);
    int lane = threadIdx.x & 31;
    if (w >= nrows) return;

    const float4* nf4 = (const float4*)nfeats;
    float sc = 1.0f + alpha[0];

    float4 a = nf4[(size_t)w * 32 + lane];
    float4 acc = make_float4(a.x * sc, a.y * sc, a.z * sc, a.w * sc);

    int cnt = g_cnt[w];
    if (cnt > PAD) cnt = PAD;
    const int* bk = &g_bucket[(size_t)w * PAD];

#define ACC_H8(u)                                                         \
    do {                                                                  \
        float2 f0 = __half22float2(h2_from_u32((u).x));                   \
        float2 f1 = __half22float2(h2_from_u32((u).y));                   \
        acc.x += f0.x; acc.y += f0.y; acc.z += f1.x; acc.w += f1.y;       \
    } while (0)

    int j = 0;
    for (; j + 4 <= cnt; j += 4) {
        int s0 = bk[j], s1 = bk[j + 1], s2 = bk[j + 2], s3 = bk[j + 3];
        uint2 v0 = g_nf16[(size_t)s0 * 32 + lane];
        uint2 v1 = g_nf16[(size_t)s1 * 32 + lane];
        uint2 v2 = g_nf16[(size_t)s2 * 32 + lane];
        uint2 v3 = g_nf16[(size_t)s3 * 32 + lane];
        ACC_H8(v0); ACC_H8(v1); ACC_H8(v2); ACC_H8(v3);
    }
    for (; j < cnt; j++) {
        uint2 v0 = g_nf16[(size_t)bk[j] * 32 + lane];
        ACC_H8(v0);
    }
#undef ACC_H8

    int novf = g_ovf_cnt;
    if (novf > 0) {
        if (novf > OVF_MAX) novf = OVF_MAX;
        for (int k = 0; k < novf; k++) {
            if (g_ovf[2 * k + 1] == w) {
                int s = g_ovf[2 * k];
                float4 u = nf4[(size_t)s * 32 + lane];
                acc.x += u.x; acc.y += u.y; acc.z += u.z; acc.w += u.w;
            }
        }
    }

    ((float4*)g_h)[(size_t)w * 32 + lane] = acc;
}

// ---- phase 3: fused 2-layer MLP, k-split W staging --------------------------
// Block: 256 threads = 32 cols x 8 row-groups, 64 rows. Inner loop is the
// proven R11 body (8 rows x 4 cols per thread, h4[8] buffered).
// smem: sW 32KB (staging for W1h0,W1h1,W2h0,W2h1) + sH 16KB (layer-1 k-half)
//       + sH1 32KB (full 64x128 layer-1 output) = 80.5KB -> 2 blocks/SM.
// Layer 2 reads sH1 directly (warp wrote its own rows -> __syncwarp only),
// saving the g_h1 gmem round-trip and a kernel launch.
#define MLP_INNER(HROW, STRIDE)                                            \
    _Pragma("unroll 2")                                                    \
    for (int k0 = 0; k0 < 64; k0 += 4) {                                   \
        float4 h4[8];                                                      \
        _Pragma("unroll")                                                  \
        for (int i = 0; i < 8; i++)                                        \
            h4[i] = *(const float4*)((HROW) + i * (STRIDE) + k0);          \
        _Pragma("unroll")                                                  \
        for (int kk = 0; kk < 4; kk++) {                                   \
            ulonglong2 wv = *(const ulonglong2*)(sW + (k0 + kk) * D + x * 4); \
            _Pragma("unroll")                                              \
            for (int i = 0; i < 8; i++) {                                  \
                float hk = (&h4[i].x)[kk];                                 \
                unsigned long long h2 = pack2(hk, hk);                     \
                a01[i] = ffma2(h2, wv.x, a01[i]);                          \
                a23[i] = ffma2(h2, wv.y, a23[i]);                          \
            }                                                              \
        }                                                                  \
    }

__global__ void __launch_bounds__(256)
k_mlp(const float* __restrict__ W1, const float* __restrict__ b1,
      const float* __restrict__ W2, const float* __restrict__ b2,
      float* __restrict__ out, int nrows) {
    extern __shared__ float smem[];
    float* sW  = smem;                 // 8192 floats (64 k-rows x 128 cols)
    float* sH  = smem + 8192;          // 4096 floats (64 rows x 64 k)
    float* sH1 = smem + 12288;         // 8192 floats (64 rows x 128 cols)

    int tid = threadIdx.x;
    int x = tid & 31;
    int y = tid >> 5;
    int row0 = blockIdx.x * 64;

    unsigned long long a01[8], a23[8];

    // ---- layer 1: relu(h @ W1 + b1) -> sH1 ----
    {
        float4 bv = *(const float4*)(b1 + x * 4);
        unsigned long long i01 = pack2(bv.x, bv.y), i23 = pack2(bv.z, bv.w);
#pragma unroll
        for (int i = 0; i < 8; i++) { a01[i] = i01; a23[i] = i23; }
    }
#pragma unroll
    for (int phase = 0; phase < 2; phase++) {
        if (phase) __syncthreads();
        {
            const float4* wg4 = (const float4*)(W1 + phase * 64 * D);
            for (int i = tid; i < 2048; i += 256) ((float4*)sW)[i] = wg4[i];
        }
        for (int i = tid; i < 1024; i += 256) {
            int r = i >> 4, c4 = i & 15;
            ((float4*)sH)[i] =
                *(const float4*)(g_h + (size_t)(row0 + r) * D + phase * 64 + c4 * 4);
        }
        __syncthreads();
        const float* hrow = sH + y * 8 * 64;
        MLP_INNER(hrow, 64)
    }
#pragma unroll
    for (int i = 0; i < 8; i++) {
        float f0, f1, f2, f3;
        unpack2(a01[i], f0, f1); unpack2(a23[i], f2, f3);
        *(float4*)(sH1 + (y * 8 + i) * D + x * 4) =
            make_float4(fmaxf(f0, 0.f), fmaxf(f1, 0.f),
                        fmaxf(f2, 0.f), fmaxf(f3, 0.f));
    }
    __syncwarp();   // warp reads back exactly the rows it wrote

    // ---- layer 2: h1 @ W2 + b2 -> out ----
    {
        float4 bv = *(const float4*)(b2 + x * 4);
        unsigned long long i01 = pack2(bv.x, bv.y), i23 = pack2(bv.z, bv.w);
#pragma unroll
        for (int i = 0; i < 8; i++) { a01[i] = i01; a23[i] = i23; }
    }
#pragma unroll
    for (int phase = 0; phase < 2; phase++) {
        __syncthreads();               // all warps done reading previous sW
        {
            const float4* wg4 = (const float4*)(W2 + phase * 64 * D);
            for (int i = tid; i < 2048; i += 256) ((float4*)sW)[i] = wg4[i];
        }
        __syncthreads();
        const float* hrow = sH1 + y * 8 * D + phase * 64;
        MLP_INNER(hrow, D)
    }
#pragma unroll
    for (int i = 0; i < 8; i++) {
        int gr = row0 + y * 8 + i;
        if (gr < nrows) {
            float f0, f1, f2, f3;
            unpack2(a01[i], f0, f1); unpack2(a23[i], f2, f3);
            *(float4*)(out + (size_t)gr * D + x * 4) =
                make_float4(f0, f1, f2, f3);
        }
    }
}

// ---------------- launch ----------------------------------------------------
#define MLP_SMEM (20480 * 4)     // 81920 bytes: sW 32K + sH 16K + sH1 32K

extern "C" void kernel_launch(void* const* d_in, const int* in_sizes, int n_in,
                              void* d_out, int out_size) {
    const float* nfeats = (const float*)d_in[0];
    const void*  src    = d_in[1];
    const void*  dst    = d_in[2];
    const float* W1     = (const float*)d_in[3];
    const float* b1     = (const float*)d_in[4];
    const float* W2     = (const float*)d_in[5];
    const float* b2     = (const float*)d_in[6];
    const float* alpha  = (const float*)d_in[7];
    float* out = (float*)d_out;

    int nE    = in_sizes[1];
    int nrows = in_sizes[0] / D;
    int n4    = nrows * (D / 4);

    int setup_items = n4 > NMAX ? n4 : NMAX;
    k_setup<<<(setup_items + 255) / 256, 256>>>(
        (const float4*)nfeats, (const unsigned int*)src, n4);
    k_dedup_fill<<<(nE + 255) / 256, 256>>>(src, dst, nE);
    k_agg<<<(nrows + 7) / 8, 256>>>(nfeats, alpha, nrows);

    cudaFuncSetAttribute(k_mlp, cudaFuncAttributeMaxDynamicSharedMemorySize,
                         MLP_SMEM);
    int nblk = (nrows + 63) / 64;
    k_mlp<<<nblk, 256, MLP_SMEM>>>(W1, b1, W2, b2, out, nrows);
}

// round 15
// speedup vs baseline: 1.2011x; 1.0569x over previous
#include <cuda_runtime.h>
#include <cuda_fp16.h>

#define D 128
#define NMAX 50048               // 782 * 64, covers MLP grid padding
#define PAD 64                   // bucket slots per dst
#define HASH_SIZE (1u << 21)
#define OVF_MAX 4096

// ---------------- device-global scratch (no allocations allowed) ------------
__device__ unsigned long long g_hash[HASH_SIZE];      // gen-tagged, never cleared
__device__ unsigned int g_gen;
__device__ float g_h[(size_t)NMAX * D];               // 25.6 MB
__device__ uint2 g_nf16[(size_t)NMAX * D / 4];        // 12.8 MB fp16 mirror
__device__ int g_cnt[NMAX];
__device__ int g_bucket[(size_t)NMAX * PAD];          // 12.8 MB
__device__ int g_ovf[OVF_MAX * 2];
__device__ int g_ovf_cnt;
__device__ int g_idx64;

// ---------------- packed f32x2 helpers (Blackwell FFMA2) --------------------
__device__ __forceinline__ unsigned long long ffma2(unsigned long long a,
                                                    unsigned long long b,
                                                    unsigned long long c) {
    unsigned long long d;
    asm("fma.rn.f32x2 %0, %1, %2, %3;" : "=l"(d) : "l"(a), "l"(b), "l"(c));
    return d;
}
__device__ __forceinline__ unsigned long long pack2(float lo, float hi) {
    unsigned long long r;
    asm("mov.b64 %0, {%1, %2};" : "=l"(r) : "f"(lo), "f"(hi));
    return r;
}
__device__ __forceinline__ void unpack2(unsigned long long v, float& lo, float& hi) {
    asm("mov.b64 {%0, %1}, %2;" : "=f"(lo), "=f"(hi) : "l"(v));
}
__device__ __forceinline__ __half2 h2_from_u32(unsigned int u) {
    return reinterpret_cast<const __half2&>(u);
}
__device__ __forceinline__ unsigned int u32_from_h2(__half2 h) {
    return reinterpret_cast<const unsigned int&>(h);
}

// ---------------- cp.async helpers (LDGSTS, sm_80+) --------------------------
__device__ __forceinline__ unsigned int smem_u32(const void* p) {
    unsigned int a;
    asm("{ .reg .u64 t; cvta.to.shared.u64 t, %1; cvt.u32.u64 %0, t; }"
        : "=r"(a) : "l"(p));
    return a;
}
__device__ __forceinline__ void cp_async16(unsigned int daddr, const void* src) {
    asm volatile("cp.async.cg.shared.global [%0], [%1], 16;"
                 :: "r"(daddr), "l"(src));
}
__device__ __forceinline__ void cp_commit() {
    asm volatile("cp.async.commit_group;" ::: "memory");
}
template <int N> __device__ __forceinline__ void cp_wait() {
    asm volatile("cp.async.wait_group %0;" :: "n"(N) : "memory");
}

// ---- phase 0: zero counts, build fp16 mirror, detect index dtype -----------
__global__ void __launch_bounds__(256)
k_setup(const float4* __restrict__ nf, const unsigned int* __restrict__ src,
        int n4) {
    int i = blockIdx.x * blockDim.x + threadIdx.x;
    if (i < n4) {
        float4 a = nf[i];
        uint2 o;
        o.x = u32_from_h2(__float22half2_rn(make_float2(a.x, a.y)));
        o.y = u32_from_h2(__float22half2_rn(make_float2(a.z, a.w)));
        g_nf16[i] = o;
    }
    if (i < NMAX) g_cnt[i] = 0;
    if (i == 0) {
        g_ovf_cnt = 0;
        g_gen = g_gen + 1;
        int is64 = 1;
#pragma unroll
        for (int k = 0; k < 8; k++)
            if (src[2 * k + 1] != 0u) is64 = 0;
        g_idx64 = is64;
    }
}

// ---- phase 1: fused dedup + bucket fill (thread per edge) ------------------
__global__ void __launch_bounds__(256)
k_dedup_fill(const void* __restrict__ srcp, const void* __restrict__ dstp,
             int nE) {
    int e = blockIdx.x * blockDim.x + threadIdx.x;
    if (e >= nE) return;
    int s, d;
    if (g_idx64) {
        s = (int)((const long long*)srcp)[e];
        d = (int)((const long long*)dstp)[e];
    } else {
        s = ((const int*)srcp)[e];
        d = ((const int*)dstp)[e];
    }

    unsigned int gen = g_gen;
    unsigned int key = ((unsigned)s << 16) | (unsigned)d;
    unsigned long long want = ((unsigned long long)gen << 32) | key;
    unsigned int slot = (key * 0x9E3779B1u) >> (32 - 21);

    for (;;) {
        unsigned long long cur;
        asm volatile("ld.global.cg.u64 %0, [%1];"
                     : "=l"(cur) : "l"(&g_hash[slot]));
        if (cur == want) return;
        if ((unsigned int)(cur >> 32) != gen) {
            unsigned long long prev = atomicCAS(&g_hash[slot], cur, want);
            if (prev == cur) break;
            if (prev == want) return;
            if ((unsigned int)(prev >> 32) != gen) continue;
        }
        slot = (slot + 1) & (HASH_SIZE - 1);
    }
    int pos = atomicAdd(&g_cnt[d], 1);
    if (pos < PAD) {
        g_bucket[(size_t)d * PAD + pos] = s;
    } else {
        int o = atomicAdd(&g_ovf_cnt, 1);
        if (o < OVF_MAX) { g_ovf[2 * o] = s; g_ovf[2 * o + 1] = d; }
    }
}

// ---- phase 2: warp-per-dst fp16 gather-sum + (1+alpha)*x + fused overflow --
__global__ void __launch_bounds__(256)
k_agg(const float* __restrict__ nfeats, const float* __restrict__ alpha,
      int nrows) {
    int w = (int)((blockIdx.x * 256u + threadIdx.x) >> 5);
    int lane = threadIdx.x & 31;
    if (w >= nrows) return;

    const float4* nf4 = (const float4*)nfeats;
    float sc = 1.0f + alpha[0];

    float4 a = nf4[(size_t)w * 32 + lane];
    float4 acc = make_float4(a.x * sc, a.y * sc, a.z * sc, a.w * sc);

    int cnt = g_cnt[w];
    if (cnt > PAD) cnt = PAD;
    const int* bk = &g_bucket[(size_t)w * PAD];

#define ACC_H8(u)                                                         \
    do {                                                                  \
        float2 f0 = __half22float2(h2_from_u32((u).x));                   \
        float2 f1 = __half22float2(h2_from_u32((u).y));                   \
        acc.x += f0.x; acc.y += f0.y; acc.z += f1.x; acc.w += f1.y;       \
    } while (0)

    int j = 0;
    for (; j + 4 <= cnt; j += 4) {
        int s0 = bk[j], s1 = bk[j + 1], s2 = bk[j + 2], s3 = bk[j + 3];
        uint2 v0 = g_nf16[(size_t)s0 * 32 + lane];
        uint2 v1 = g_nf16[(size_t)s1 * 32 + lane];
        uint2 v2 = g_nf16[(size_t)s2 * 32 + lane];
        uint2 v3 = g_nf16[(size_t)s3 * 32 + lane];
        ACC_H8(v0); ACC_H8(v1); ACC_H8(v2); ACC_H8(v3);
    }
    for (; j < cnt; j++) {
        uint2 v0 = g_nf16[(size_t)bk[j] * 32 + lane];
        ACC_H8(v0);
    }
#undef ACC_H8

    int novf = g_ovf_cnt;
    if (novf > 0) {
        if (novf > OVF_MAX) novf = OVF_MAX;
        for (int k = 0; k < novf; k++) {
            if (g_ovf[2 * k + 1] == w) {
                int s = g_ovf[2 * k];
                float4 u = nf4[(size_t)s * 32 + lane];
                acc.x += u.x; acc.y += u.y; acc.z += u.z; acc.w += u.w;
            }
        }
    }

    ((float4*)g_h)[(size_t)w * 32 + lane] = acc;
}

// ---- phase 3: fused 2-layer MLP, cp.async double-buffered W staging --------
// smem: sWa 32K + sWb 32K + sH 16K + sH1 32K = 112KB -> 2 blocks/SM.
// W fills stream in the background (cp.async) while the FFMA2 inner loop
// (proven R11/R14 body) computes from the other buffer.
#define MLP_INNER(SW, HROW, STRIDE)                                        \
    _Pragma("unroll 2")                                                    \
    for (int k0 = 0; k0 < 64; k0 += 4) {                                   \
        float4 h4[8];                                                      \
        _Pragma("unroll")                                                  \
        for (int i = 0; i < 8; i++)                                        \
            h4[i] = *(const float4*)((HROW) + i * (STRIDE) + k0);          \
        _Pragma("unroll")                                                  \
        for (int kk = 0; kk < 4; kk++) {                                   \
            ulonglong2 wv =                                                \
                *(const ulonglong2*)((SW) + (k0 + kk) * D + x * 4);        \
            _Pragma("unroll")                                              \
            for (int i = 0; i < 8; i++) {                                  \
                float hk = (&h4[i].x)[kk];                                 \
                unsigned long long h2 = pack2(hk, hk);                     \
                a01[i] = ffma2(h2, wv.x, a01[i]);                          \
                a23[i] = ffma2(h2, wv.y, a23[i]);                          \
            }                                                              \
        }                                                                  \
    }

__device__ __forceinline__ void cpW(float* dst, const float* src, int tid) {
    unsigned int d0 = smem_u32(dst);
    const float4* s4 = (const float4*)src;
#pragma unroll
    for (int i = 0; i < 8; i++)
        cp_async16(d0 + (tid + 256 * i) * 16, &s4[tid + 256 * i]);
}
__device__ __forceinline__ void cpH(float* dst, const float* gin, int row0,
                                    int koff, int tid) {
    unsigned int d0 = smem_u32(dst);
#pragma unroll
    for (int j = 0; j < 4; j++) {
        int i = tid + 256 * j;
        int r = i >> 4, c4 = i & 15;
        cp_async16(d0 + i * 16,
                   gin + (size_t)(row0 + r) * D + koff + c4 * 4);
    }
}

__global__ void __launch_bounds__(256)
k_mlp(const float* __restrict__ W1, const float* __restrict__ b1,
      const float* __restrict__ W2, const float* __restrict__ b2,
      float* __restrict__ out, int nrows) {
    extern __shared__ float smem[];
    float* sWa = smem;                 // 8192 floats
    float* sWb = smem + 8192;          // 8192 floats
    float* sH  = smem + 16384;         // 4096 floats (64 rows x 64 k)
    float* sH1 = smem + 20480;         // 8192 floats (64 rows x 128 cols)

    int tid = threadIdx.x;
    int x = tid & 31;
    int y = tid >> 5;
    int row0 = blockIdx.x * 64;

    // g0: sWa <- W1h0 + sH <- Hh0 ; g1: sWb <- W1h1
    cpW(sWa, W1, tid);
    cpH(sH, g_h, row0, 0, tid);
    cp_commit();
    cpW(sWb, W1 + 64 * D, tid);
    cp_commit();

    unsigned long long a01[8], a23[8];
    {
        float4 bv = *(const float4*)(b1 + x * 4);
        unsigned long long i01 = pack2(bv.x, bv.y), i23 = pack2(bv.z, bv.w);
#pragma unroll
        for (int i = 0; i < 8; i++) { a01[i] = i01; a23[i] = i23; }
    }

    cp_wait<1>();              // g0 done (sWa, sH)
    __syncthreads();
    {   // layer 1, phase 0 (sWa, sH); sWb streaming in background
        const float* hrow = sH + y * 8 * 64;
        MLP_INNER(sWa, hrow, 64)
    }
    cp_wait<0>();              // g1 done (sWb)
    __syncthreads();           // all warps done reading sH & sWa

    // g2: sH <- Hh1 ; g3: sWa <- W2h0 (background for layer 2)
    cpH(sH, g_h, row0, 64, tid);
    cp_commit();
    cpW(sWa, W2, tid);
    cp_commit();
    cp_wait<1>();              // g2 done (sH refilled); g3 in flight
    __syncthreads();
    {   // layer 1, phase 1 (sWb, sH)
        const float* hrow = sH + y * 8 * 64;
        MLP_INNER(sWb, hrow, 64)
    }

    // epilogue layer 1 -> sH1 (own rows; read back by same warp)
#pragma unroll
    for (int i = 0; i < 8; i++) {
        float f0, f1, f2, f3;
        unpack2(a01[i], f0, f1); unpack2(a23[i], f2, f3);
        *(float4*)(sH1 + (y * 8 + i) * D + x * 4) =
            make_float4(fmaxf(f0, 0.f), fmaxf(f1, 0.f),
                        fmaxf(f2, 0.f), fmaxf(f3, 0.f));
    }
    __syncwarp();

    {
        float4 bv = *(const float4*)(b2 + x * 4);
        unsigned long long i01 = pack2(bv.x, bv.y), i23 = pack2(bv.z, bv.w);
#pragma unroll
        for (int i = 0; i < 8; i++) { a01[i] = i01; a23[i] = i23; }
    }

    cp_wait<0>();              // g3 done (sWa = W2h0)
    __syncthreads();           // all warps done reading sWb (layer-1 ph1)
    // g4: sWb <- W2h1 (background)
    cpW(sWb, W2 + 64 * D, tid);
    cp_commit();
    {   // layer 2, phase 0 (sWa, sH1 cols 0..64)
        const float* hrow = sH1 + y * 8 * D;
        MLP_INNER(sWa, hrow, D)
    }
    cp_wait<0>();              // g4 done (sWb = W2h1)
    __syncthreads();
    {   // layer 2, phase 1 (sWb, sH1 cols 64..128)
        const float* hrow = sH1 + y * 8 * D + 64;
        MLP_INNER(sWb, hrow, D)
    }

#pragma unroll
    for (int i = 0; i < 8; i++) {
        int gr = row0 + y * 8 + i;
        if (gr < nrows) {
            float f0, f1, f2, f3;
            unpack2(a01[i], f0, f1); unpack2(a23[i], f2, f3);
            *(float4*)(out + (size_t)gr * D + x * 4) =
                make_float4(f0, f1, f2, f3);
        }
    }
}

// ---------------- launch ----------------------------------------------------
#define MLP_SMEM (28672 * 4)     // 114688 bytes: sWa 32K + sWb 32K + sH 16K + sH1 32K

extern "C" void kernel_launch(void* const* d_in, const int* in_sizes, int n_in,
                              void* d_out, int out_size) {
    const float* nfeats = (const float*)d_in[0];
    const void*  src    = d_in[1];
    const void*  dst    = d_in[2];
    const float* W1     = (const float*)d_in[3];
    const float* b1     = (const float*)d_in[4];
    const float* W2     = (const float*)d_in[5];
    const float* b2     = (const float*)d_in[6];
    const float* alpha  = (const float*)d_in[7];
    float* out = (float*)d_out;

    int nE    = in_sizes[1];
    int nrows = in_sizes[0] / D;
    int n4    = nrows * (D / 4);

    int setup_items = n4 > NMAX ? n4 : NMAX;
    k_setup<<<(setup_items + 255) / 256, 256>>>(
        (const float4*)nfeats, (const unsigned int*)src, n4);
    k_dedup_fill<<<(nE + 255) / 256, 256>>>(src, dst, nE);
    k_agg<<<(nrows + 7) / 8, 256>>>(nfeats, alpha, nrows);

    cudaFuncSetAttribute(k_mlp, cudaFuncAttributeMaxDynamicSharedMemorySize,
                         MLP_SMEM);
    int nblk = (nrows + 63) / 64;
    k_mlp<<<nblk, 256, MLP_SMEM>>>(W1, b1, W2, b2, out, nrows);
}